// round 1
// baseline (speedup 1.0000x reference)
#include <cuda_runtime.h>
#include <cstdint>

#define B_    8
#define CIN   32
#define COUT  32
#define H_    96
#define W_    96
#define K_    5
#define P_    2

#define TILE_X 32
#define TILE_Y 16
#define CCHUNK 4
#define NEG (-1.70141173e38f)   // -FLT_MAX/2

// Block: 256 threads. Each thread: 4 o-channels x 4 x-pixels.
// Block covers: 8 o-channels x 16 y x 32 x  = 4096 outputs.
// Grid: (96/32, 96/16, B * COUT/8) = (3, 6, 32) = 576 blocks.

__global__ __launch_bounds__(256) void dilate2d_kernel(
    const float* __restrict__ f,
    const float* __restrict__ h,
    float* __restrict__ out)
{
    __shared__ __align__(16) float sw[CIN][K_ * K_][8];              // [c][ij][o_local] 25.6 KB
    __shared__ __align__(16) float sf[CCHUNK][TILE_Y + 4][TILE_X + 4]; // 11.5 KB

    const int tid = threadIdx.x;
    const int tx  = tid & 7;          // x group: 8 groups of 4 px
    const int ty  = (tid >> 3) & 15;  // y row within tile
    const int tg  = tid >> 7;         // o group: 0 or 1 (4 o's each)

    const int bx = blockIdx.x;            // 0..2
    const int by = blockIdx.y;            // 0..5
    const int bz = blockIdx.z;            // 0..31 = b*4 + ogroup
    const int b     = bz >> 2;
    const int oBase = (bz & 3) * 8;

    const int x0 = bx * TILE_X;
    const int y0 = by * TILE_Y;

    // ---- Load weights for this block's 8 o-channels, transposed to [c][ij][o] ----
    // Global read pattern: consecutive tid -> consecutive (c,ij) => coalesced.
    for (int idx = tid; idx < CIN * K_ * K_ * 8; idx += 256) {
        const int o_local = idx / (CIN * K_ * K_);
        const int cij     = idx % (CIN * K_ * K_);
        const int c  = cij / (K_ * K_);
        const int ij = cij % (K_ * K_);
        sw[c][ij][o_local] = h[(size_t)(oBase + o_local) * (CIN * K_ * K_) + cij];
    }

    float acc[4][4];
    #pragma unroll
    for (int oo = 0; oo < 4; oo++)
        #pragma unroll
        for (int d = 0; d < 4; d++)
            acc[oo][d] = NEG;

    const float* fb = f + (size_t)b * CIN * H_ * W_;

    #pragma unroll 1
    for (int c0 = 0; c0 < CIN; c0 += CCHUNK) {
        __syncthreads();   // protect previous chunk's sf + (first iter) publish sw

        // ---- Stage CCHUNK channels of the padded f tile into smem ----
        constexpr int TILE_ELEMS = CCHUNK * (TILE_Y + 4) * (TILE_X + 4);
        for (int idx = tid; idx < TILE_ELEMS; idx += 256) {
            const int cc  = idx / ((TILE_Y + 4) * (TILE_X + 4));
            const int rem = idx % ((TILE_Y + 4) * (TILE_X + 4));
            const int r   = rem / (TILE_X + 4);
            const int col = rem % (TILE_X + 4);
            const int gy = y0 - P_ + r;
            const int gx = x0 - P_ + col;
            float v = NEG;
            if ((unsigned)gy < (unsigned)H_ && (unsigned)gx < (unsigned)W_)
                v = fb[(size_t)(c0 + cc) * (H_ * W_) + gy * W_ + gx];
            sf[cc][r][col] = v;
        }
        __syncthreads();

        // ---- Compute: 4 channels x 5 rows x 5 cols ----
        #pragma unroll 1
        for (int cc = 0; cc < CCHUNK; cc++) {
            const int c = c0 + cc;
            #pragma unroll
            for (int i = 0; i < K_; i++) {
                // 8-float window (2 aligned LDS.128); sliding windows reuse regs across j
                const float4* prow =
                    reinterpret_cast<const float4*>(&sf[cc][ty + i][tx * 4]);
                const float4 fa = prow[0];
                const float4 fbv = prow[1];
                const float fr[8] = { fa.x, fa.y, fa.z, fa.w,
                                      fbv.x, fbv.y, fbv.z, fbv.w };
                #pragma unroll
                for (int j = 0; j < K_; j++) {
                    const float4 w4 =
                        *reinterpret_cast<const float4*>(&sw[c][i * K_ + j][tg * 4]);
                    const float wv[4] = { w4.x, w4.y, w4.z, w4.w };
                    #pragma unroll
                    for (int oo = 0; oo < 4; oo++) {
                        #pragma unroll
                        for (int d = 0; d < 4; d++) {
                            acc[oo][d] = fmaxf(acc[oo][d], fr[j + d] + wv[oo]);
                        }
                    }
                }
            }
        }
    }

    // ---- Write out: 4 float4 stores per thread, coalesced across tx ----
    float* ob = out + (size_t)b * COUT * H_ * W_;
    #pragma unroll
    for (int oo = 0; oo < 4; oo++) {
        const int o = oBase + tg * 4 + oo;
        float4 v = make_float4(acc[oo][0], acc[oo][1], acc[oo][2], acc[oo][3]);
        *reinterpret_cast<float4*>(
            &ob[(size_t)o * (H_ * W_) + (size_t)(y0 + ty) * W_ + x0 + tx * 4]) = v;
    }
}

extern "C" void kernel_launch(void* const* d_in, const int* in_sizes, int n_in,
                              void* d_out, int out_size)
{
    const float* f = (const float*)d_in[0];
    const float* h = (const float*)d_in[1];
    float* out = (float*)d_out;

    dim3 grid(W_ / TILE_X, H_ / TILE_Y, B_ * (COUT / 8));  // (3, 6, 32)
    dim3 block(256);
    dilate2d_kernel<<<grid, block>>>(f, h, out);
}

// round 2
// speedup vs baseline: 1.5498x; 1.5498x over previous
#include <cuda_runtime.h>
#include <cuda_fp16.h>
#include <cstdint>

#define B_    8
#define CIN   32
#define COUT  32
#define H_    96
#define W_    96
#define K_    5
#define P_    2

#define TILE_X 32
#define TILE_Y 16
#define CCHUNK 4
#define SHIFT  3.0f

// Block: 128 threads. thread = (xg 0..3, ty 0..15, tg 0..1).
// Each thread: 8 x-pixels (4 half2 pairs) x 4 o-channels.
// Block covers 8 o x 16 y x 32 x. Grid (3, 6, B*4) = 576 blocks.

union U32H2 { uint32_t u; __half2 h; };

__device__ __forceinline__ __half2 h2_of(uint32_t v) { U32H2 t; t.u = v; return t.h; }

__global__ __launch_bounds__(128) void dilate2d_h2_kernel(
    const float* __restrict__ f,
    const float* __restrict__ h,
    float* __restrict__ out)
{
    // Weights duplicated as (w,w) half2 so one broadcast LDS.128 feeds 4 o's.
    __shared__ __align__(16) __half2 sw2[CIN][K_ * K_][8];            // 25.6 KB
    __shared__ __align__(16) __half  sf[CCHUNK][TILE_Y + 4][40];      // 6.4 KB (36 used)

    const int tid = threadIdx.x;
    const int xg  = tid & 3;           // x group: 8 px each
    const int ty  = (tid >> 2) & 15;   // y row
    const int tg  = tid >> 6;          // o group (4 o's each)

    const int bz = blockIdx.z;
    const int b     = bz >> 2;
    const int oBase = (bz & 3) * 8;
    const int x0 = blockIdx.x * TILE_X;
    const int y0 = blockIdx.y * TILE_Y;

    const __half negh = __float2half(-1000.0f);

    // ---- Stage weights: fp32 -> duplicated half2, transposed to [c][ij][o] ----
    for (int idx = tid; idx < CIN * K_ * K_ * 8; idx += 128) {
        const int o_local = idx / (CIN * K_ * K_);
        const int cij     = idx % (CIN * K_ * K_);
        const int c  = cij / (K_ * K_);
        const int ij = cij % (K_ * K_);
        const float wv = h[(size_t)(oBase + o_local) * (CIN * K_ * K_) + cij];
        sw2[c][ij][o_local] = __half2half2(__float2half(wv));
    }

    __half2 acc[4][4];   // [oo][pixel-pair]
    const __half2 negh2 = __half2half2(negh);
    #pragma unroll
    for (int oo = 0; oo < 4; oo++)
        #pragma unroll
        for (int p = 0; p < 4; p++)
            acc[oo][p] = negh2;

    const float* fb = f + (size_t)b * CIN * H_ * W_;

    #pragma unroll 1
    for (int c0 = 0; c0 < CIN; c0 += CCHUNK) {
        if (c0) __syncthreads();   // previous chunk's compute done

        // ---- Stage CCHUNK channels, shifted by -3 and converted to fp16 ----
        for (int idx = tid; idx < CCHUNK * (TILE_Y + 4) * 36; idx += 128) {
            const int cc  = idx / ((TILE_Y + 4) * 36);
            const int rem = idx % ((TILE_Y + 4) * 36);
            const int r   = rem / 36;
            const int col = rem % 36;
            const int gy = y0 - P_ + r;
            const int gx = x0 - P_ + col;
            __half v = negh;
            if ((unsigned)gy < (unsigned)H_ && (unsigned)gx < (unsigned)W_)
                v = __float2half(fb[(size_t)(c0 + cc) * (H_ * W_) + gy * W_ + gx] - SHIFT);
            sf[cc][r][col] = v;
        }
        __syncthreads();   // first iteration also publishes sw2

        #pragma unroll 1
        for (int cc = 0; cc < CCHUNK; cc++) {
            const int c = c0 + cc;
            #pragma unroll 1
            for (int i = 0; i < K_; i++) {
                // 12-half window: halves [xg*8 .. xg*8+11] -> LDS.128 + LDS.64
                const __half* rowp = &sf[cc][ty + i][xg * 8];
                const uint4 va = *reinterpret_cast<const uint4*>(rowp);
                const uint2 vb = *reinterpret_cast<const uint2*>(rowp + 8);
                // aligned even pairs (h0,h1)..(h10,h11)
                const uint32_t eu[6] = { va.x, va.y, va.z, va.w, vb.x, vb.y };
                // odd sliding pairs (h1,h2),(h3,h4),(h5,h6),(h7,h8),(h9,h10)
                uint32_t ou[5];
                #pragma unroll
                for (int k = 0; k < 5; k++)
                    ou[k] = __byte_perm(eu[k], eu[k + 1], 0x5432);

                #pragma unroll
                for (int j = 0; j < K_; j++) {
                    const uint4 wraw =
                        *reinterpret_cast<const uint4*>(&sw2[c][i * K_ + j][tg * 4]);
                    const __half2 w2[4] = { h2_of(wraw.x), h2_of(wraw.y),
                                            h2_of(wraw.z), h2_of(wraw.w) };
                    #pragma unroll
                    for (int p = 0; p < 4; p++) {
                        // candidate pair (fr[j+2p], fr[j+2p+1])
                        const __half2 fp = (j & 1) ? h2_of(ou[((j - 1) >> 1) + p])
                                                   : h2_of(eu[(j >> 1) + p]);
                        #pragma unroll
                        for (int oo = 0; oo < 4; oo++) {
                            acc[oo][p] = __hmax2(acc[oo][p], __hadd2(fp, w2[oo]));
                        }
                    }
                }
            }
        }
    }

    // ---- Epilogue: fp16 -> fp32, add shift back, 2x float4 store per o ----
    #pragma unroll
    for (int oo = 0; oo < 4; oo++) {
        const int o = oBase + tg * 4 + oo;
        float* op = out + ((size_t)b * COUT + o) * (H_ * W_)
                        + (size_t)(y0 + ty) * W_ + x0 + xg * 8;
        float4 v0 = make_float4(__low2float(acc[oo][0]) + SHIFT,
                                __high2float(acc[oo][0]) + SHIFT,
                                __low2float(acc[oo][1]) + SHIFT,
                                __high2float(acc[oo][1]) + SHIFT);
        float4 v1 = make_float4(__low2float(acc[oo][2]) + SHIFT,
                                __high2float(acc[oo][2]) + SHIFT,
                                __low2float(acc[oo][3]) + SHIFT,
                                __high2float(acc[oo][3]) + SHIFT);
        reinterpret_cast<float4*>(op)[0] = v0;
        reinterpret_cast<float4*>(op)[1] = v1;
    }
}

extern "C" void kernel_launch(void* const* d_in, const int* in_sizes, int n_in,
                              void* d_out, int out_size)
{
    const float* f = (const float*)d_in[0];
    const float* h = (const float*)d_in[1];
    float* out = (float*)d_out;

    dim3 grid(W_ / TILE_X, H_ / TILE_Y, B_ * 4);  // (3, 6, 32)
    dim3 block(128);
    dilate2d_h2_kernel<<<grid, block>>>(f, h, out);
}